// round 3
// baseline (speedup 1.0000x reference)
#include <cuda_runtime.h>
#include <cstdint>

#define HDIM 64
#define NOBJ 25
#define ROWF 100          // floats per sample in canvas (25*4)
#define SAMPLES_PER_CTA 64
#define SMEM_BYTES (65536 + 17408 + 25600)   // Wq + h(64x68) + seq(64x25 float4) = 108544

// Device-global scratch (no allocations allowed)
__device__ int    g_Tmax;
__device__ float4 g_Wq[64 * 64];   // [k][j] = (W_i, W_f, W_g, W_o) at (row g*64+j, col k) of W_hh
__device__ float4 g_Aq[4 * 64];    // [d][j] = per-gate coefficient of x_d  (A = W_ih @ W_emb)
__device__ float4 g_Bq[64];        // [j]    = per-gate total bias (W_ih@b_emb + b_ih + b_hh)

// ---------------- f32x2 helpers (Blackwell packed fp32 FMA) ----------------
__device__ __forceinline__ unsigned long long pack2(float a, float b) {
    unsigned long long r;
    asm("mov.b64 %0, {%1, %2};" : "=l"(r) : "f"(a), "f"(b));
    return r;
}
__device__ __forceinline__ void unpack2(unsigned long long v, float& lo, float& hi) {
    asm("mov.b64 {%0, %1}, %2;" : "=f"(lo), "=f"(hi) : "l"(v));
}
__device__ __forceinline__ unsigned long long ffma2(unsigned long long a,
                                                    unsigned long long b,
                                                    unsigned long long c) {
#if defined(__CUDA_ARCH__) && (__CUDA_ARCH__ >= 1000)
    unsigned long long d;
    asm("fma.rn.f32x2 %0, %1, %2, %3;" : "=l"(d) : "l"(a), "l"(b), "l"(c));
    return d;
#else
    float alo, ahi, blo, bhi, clo, chi;
    unpack2(a, alo, ahi); unpack2(b, blo, bhi); unpack2(c, clo, chi);
    return pack2(fmaf(alo, blo, clo), fmaf(ahi, bhi, chi));
#endif
}

__device__ __forceinline__ float sigm(float x) {
    return __fdividef(1.0f, 1.0f + __expf(-x));
}
__device__ __forceinline__ float tanh_fast(float x) {
    return __fdividef(2.0f, 1.0f + __expf(-2.0f * x)) - 1.0f;
}

// ---------------- Kernel 0: fold Linear into LSTM input path, repack W_hh ----------------
__global__ void precompute_kernel(const float* __restrict__ W_emb, const float* __restrict__ b_emb,
                                  const float* __restrict__ W_ih,  const float* __restrict__ W_hh,
                                  const float* __restrict__ b_ih,  const float* __restrict__ b_hh) {
    const int tid = threadIdx.x;  // 256 threads
    if (tid == 0) g_Tmax = 0;     // reset max each launch (stream-ordered before count_kernel)

    // Repack W_hh (256,64) into gate-interleaved [k][j] float4
    for (int idx = tid; idx < 64 * 64; idx += 256) {
        const int k = idx >> 6, j = idx & 63;
        float4 w;
        w.x = W_hh[(0 * 64 + j) * 64 + k];
        w.y = W_hh[(1 * 64 + j) * 64 + k];
        w.z = W_hh[(2 * 64 + j) * 64 + k];
        w.w = W_hh[(3 * 64 + j) * 64 + k];
        g_Wq[idx] = w;
    }

    // A[r][d] = sum_k W_ih[r][k] * W_emb[k][d];  bias[r] = sum_k W_ih[r][k]*b_emb[k] + b_ih[r] + b_hh[r]
    if (tid < 64) {
        const int j = tid;
        float acc[4][5];
        #pragma unroll
        for (int g = 0; g < 4; g++)
            #pragma unroll
            for (int d = 0; d < 5; d++) acc[g][d] = 0.0f;
        for (int k = 0; k < 64; k++) {
            const float be = b_emb[k];
            #pragma unroll
            for (int g = 0; g < 4; g++) {
                const float wih = W_ih[(g * 64 + j) * 64 + k];
                #pragma unroll
                for (int d = 0; d < 4; d++) acc[g][d] = fmaf(wih, W_emb[k * 4 + d], acc[g][d]);
                acc[g][4] = fmaf(wih, be, acc[g][4]);
            }
        }
        #pragma unroll
        for (int d = 0; d < 4; d++)
            g_Aq[d * 64 + j] = make_float4(acc[0][d], acc[1][d], acc[2][d], acc[3][d]);
        g_Bq[j] = make_float4(acc[0][4] + b_ih[0 * 64 + j] + b_hh[0 * 64 + j],
                              acc[1][4] + b_ih[1 * 64 + j] + b_hh[1 * 64 + j],
                              acc[2][4] + b_ih[2 * 64 + j] + b_hh[2 * 64 + j],
                              acc[3][4] + b_ih[3 * 64 + j] + b_hh[3 * 64 + j]);
    }
}

// ---------------- Kernel 1: global T_max = max over batch of valid-object count ----------------
__global__ void count_kernel(const float* __restrict__ canvas, int B) {
    __shared__ int smax;
    if (threadIdx.x == 0) smax = 0;
    __syncthreads();

    const int warp = blockIdx.x * (blockDim.x >> 5) + (threadIdx.x >> 5);
    const int lane = threadIdx.x & 31;
    if (warp < B) {
        int valid = 0;
        if (lane < NOBJ) {
            const float4 v = *reinterpret_cast<const float4*>(canvas + (size_t)warp * ROWF + lane * 4);
            const float s = ((v.x + v.y) + v.z) + v.w;
            valid = (s >= 0.0f) ? 1 : 0;
        }
        const unsigned msk = __ballot_sync(0xFFFFFFFFu, valid);
        const int cnt = __popc(msk);
        if (lane == 0 && cnt > 0) atomicMax(&smax, cnt);
    }
    __syncthreads();
    if (threadIdx.x == 0 && smax > 0) atomicMax(&g_Tmax, smax);
}

// ---------------- Kernel 2: fused compaction + LSTM (64 samples per CTA) ----------------
// Thread layout: j = tid&63 (hidden unit), sg = tid>>6 (sample subgroup of 16 samples).
// Each thread keeps h,c for its 16 samples in registers; h is exchanged via smem each step.
// Inner matvec uses packed fma.rn.f32x2 over sample pairs; W duplicated into both halves.
__global__ void __launch_bounds__(256, 1) lstm_kernel(const float* __restrict__ canvas,
                                                      float* __restrict__ out, int B) {
    extern __shared__ char smem[];
    float4* sWq  = reinterpret_cast<float4*>(smem);                  // 64x64 float4 = 65536 B
    float*  sH   = reinterpret_cast<float*>(smem + 65536);           // [64][68] floats = 17408 B
    float4* sSeq = reinterpret_cast<float4*>(smem + 82944);          // [64][25] float4 = 25600 B

    const int tid     = threadIdx.x;
    const int j       = tid & 63;
    const int sg      = tid >> 6;       // 0..3
    const int sgBase  = sg * 16;
    const int ctaBase = blockIdx.x * SAMPLES_PER_CTA;

    // Load repacked W_hh into smem (coalesced)
    #pragma unroll
    for (int i = 0; i < 16; i++) sWq[tid + i * 256] = g_Wq[tid + i * 256];

    // Zero h buffer
    for (int i = tid; i < 64 * 68; i += 256) sH[i] = 0.0f;

    // Compaction: 8 warps, 8 samples each. Stable-compact valid rows, pad with -1.
    {
        const int w = tid >> 5, lane = tid & 31;
        #pragma unroll
        for (int m = 0; m < 8; m++) {
            const int s = w * 8 + m;
            const int b = ctaBase + s;
            float4 v = make_float4(-1.0f, -1.0f, -1.0f, -1.0f);
            int valid = 0;
            if (b < B && lane < NOBJ) {
                v = *reinterpret_cast<const float4*>(canvas + (size_t)b * ROWF + lane * 4);
                const float sum = ((v.x + v.y) + v.z) + v.w;
                valid = (sum >= 0.0f) ? 1 : 0;
            }
            const unsigned msk = __ballot_sync(0xFFFFFFFFu, valid);
            const int cnt = __popc(msk);
            if (lane < NOBJ) {
                if (valid) {
                    const int pos = __popc(msk & ((1u << lane) - 1u));
                    sSeq[s * NOBJ + pos] = v;
                }
                if (lane >= cnt) sSeq[s * NOBJ + lane] = make_float4(-1.0f, -1.0f, -1.0f, -1.0f);
            }
        }
    }

    // Hoist folded input coefficients into registers
    const float4 A0 = g_Aq[0 * 64 + j];
    const float4 A1 = g_Aq[1 * 64 + j];
    const float4 A2 = g_Aq[2 * 64 + j];
    const float4 A3 = g_Aq[3 * 64 + j];
    const float4 Bq = g_Bq[j];

    float h[16], c[16];
    #pragma unroll
    for (int m = 0; m < 16; m++) { h[m] = 0.0f; c[m] = 0.0f; }

    const int T = g_Tmax;
    __syncthreads();

    for (int t = 0; t < T; t++) {
        unsigned long long ai[8], af[8], ag[8], ao[8];

        // x-side: gate preactivation init from compacted (or pad) object features
        #pragma unroll
        for (int p = 0; p < 8; p++) {
            const float4 xa = sSeq[(sgBase + 2 * p) * NOBJ + t];
            const float4 xb = sSeq[(sgBase + 2 * p + 1) * NOBJ + t];
            const float i0 = fmaf(A3.x, xa.w, fmaf(A2.x, xa.z, fmaf(A1.x, xa.y, fmaf(A0.x, xa.x, Bq.x))));
            const float f0 = fmaf(A3.y, xa.w, fmaf(A2.y, xa.z, fmaf(A1.y, xa.y, fmaf(A0.y, xa.x, Bq.y))));
            const float g0 = fmaf(A3.z, xa.w, fmaf(A2.z, xa.z, fmaf(A1.z, xa.y, fmaf(A0.z, xa.x, Bq.z))));
            const float o0 = fmaf(A3.w, xa.w, fmaf(A2.w, xa.z, fmaf(A1.w, xa.y, fmaf(A0.w, xa.x, Bq.w))));
            const float i1 = fmaf(A3.x, xb.w, fmaf(A2.x, xb.z, fmaf(A1.x, xb.y, fmaf(A0.x, xb.x, Bq.x))));
            const float f1 = fmaf(A3.y, xb.w, fmaf(A2.y, xb.z, fmaf(A1.y, xb.y, fmaf(A0.y, xb.x, Bq.y))));
            const float g1 = fmaf(A3.z, xb.w, fmaf(A2.z, xb.z, fmaf(A1.z, xb.y, fmaf(A0.z, xb.x, Bq.z))));
            const float o1 = fmaf(A3.w, xb.w, fmaf(A2.w, xb.z, fmaf(A1.w, xb.y, fmaf(A0.w, xb.x, Bq.w))));
            ai[p] = pack2(i0, i1); af[p] = pack2(f0, f1);
            ag[p] = pack2(g0, g1); ao[p] = pack2(o0, o1);
        }

        // Recurrent matvec: gates += W_hh * h  (packed f32x2, 16 samples per thread)
        #pragma unroll 4
        for (int k = 0; k < 64; k++) {
            const float4 wv = sWq[k * 64 + j];
            const unsigned long long wi = pack2(wv.x, wv.x);
            const unsigned long long wf = pack2(wv.y, wv.y);
            const unsigned long long wg = pack2(wv.z, wv.z);
            const unsigned long long wo = pack2(wv.w, wv.w);
            const ulonglong2* hp = reinterpret_cast<const ulonglong2*>(sH + k * 68 + sgBase);
            #pragma unroll
            for (int q = 0; q < 4; q++) {
                const ulonglong2 h4 = hp[q];     // 4 samples per 16B broadcast load
                ai[2 * q]     = ffma2(wi, h4.x, ai[2 * q]);
                af[2 * q]     = ffma2(wf, h4.x, af[2 * q]);
                ag[2 * q]     = ffma2(wg, h4.x, ag[2 * q]);
                ao[2 * q]     = ffma2(wo, h4.x, ao[2 * q]);
                ai[2 * q + 1] = ffma2(wi, h4.y, ai[2 * q + 1]);
                af[2 * q + 1] = ffma2(wf, h4.y, af[2 * q + 1]);
                ag[2 * q + 1] = ffma2(wg, h4.y, ag[2 * q + 1]);
                ao[2 * q + 1] = ffma2(wo, h4.y, ao[2 * q + 1]);
            }
        }

        // Nonlinearity + state update (torch gate order i,f,g,o)
        #pragma unroll
        for (int p = 0; p < 8; p++) {
            float iv0, iv1, fv0, fv1, gv0, gv1, ov0, ov1;
            unpack2(ai[p], iv0, iv1); unpack2(af[p], fv0, fv1);
            unpack2(ag[p], gv0, gv1); unpack2(ao[p], ov0, ov1);
            const int m0 = 2 * p, m1 = 2 * p + 1;
            const float c0 = sigm(fv0) * c[m0] + sigm(iv0) * tanh_fast(gv0);
            c[m0] = c0; h[m0] = sigm(ov0) * tanh_fast(c0);
            const float c1 = sigm(fv1) * c[m1] + sigm(iv1) * tanh_fast(gv1);
            c[m1] = c1; h[m1] = sigm(ov1) * tanh_fast(c1);
        }

        __syncthreads();   // all reads of old h done
        #pragma unroll
        for (int q = 0; q < 4; q++) {
            *reinterpret_cast<float4*>(sH + j * 68 + sgBase + 4 * q) =
                make_float4(h[4 * q], h[4 * q + 1], h[4 * q + 2], h[4 * q + 3]);
        }
        __syncthreads();   // new h visible
    }

    // Final h write (coalesced: 64 consecutive units per sample across 2 warps)
    #pragma unroll
    for (int m = 0; m < 16; m++) {
        const int b = ctaBase + sgBase + m;
        if (b < B) out[(size_t)b * HDIM + j] = h[m];
    }
}

// ---------------- launch ----------------
extern "C" void kernel_launch(void* const* d_in, const int* in_sizes, int n_in,
                              void* d_out, int out_size) {
    const float* canvas = (const float*)d_in[0];
    const float* W_emb  = (const float*)d_in[1];
    const float* b_emb  = (const float*)d_in[2];
    const float* W_ih   = (const float*)d_in[3];
    const float* W_hh   = (const float*)d_in[4];
    const float* b_ih   = (const float*)d_in[5];
    const float* b_hh   = (const float*)d_in[6];
    float* out = (float*)d_out;

    const int B = in_sizes[0] / ROWF;

    cudaFuncSetAttribute(lstm_kernel, cudaFuncAttributeMaxDynamicSharedMemorySize, SMEM_BYTES);

    precompute_kernel<<<1, 256>>>(W_emb, b_emb, W_ih, W_hh, b_ih, b_hh);
    count_kernel<<<(B + 7) / 8, 256>>>(canvas, B);
    lstm_kernel<<<(B + SAMPLES_PER_CTA - 1) / SAMPLES_PER_CTA, 256, SMEM_BYTES>>>(canvas, out, B);
}